// round 5
// baseline (speedup 1.0000x reference)
#include <cuda_runtime.h>

// Problem constants
#define NBATCH 64
#define NBINS  256
#define ELEMS_PER_BATCH (256*32*32)          // 262144 floats per batch per tensor
#define F4_PER_BATCH    (ELEMS_PER_BATCH/4)  // 65536 float4
#define CHUNKS 4                             // blocks per (batch, tensor)
#define F4_PER_CHUNK (F4_PER_BATCH/CHUNKS)   // 16384 float4 per block
#define HIST_THREADS 512
#define WARPS_PER_BLOCK (HIST_THREADS/32)    // 16
#define BLOCKS_PER_BATCH (2*CHUNKS)          // 8 (both tensors)

// Scratch (no device allocation allowed).
// Partials are STORED (not accumulated) -> no zeroing pass needed.
__device__ unsigned int g_part[2][NBATCH][CHUNKS][NBINS];
__device__ float        g_kl[NBATCH];
__device__ unsigned int g_bctr[NBATCH];      // per-batch tickets (reset by winner)
__device__ unsigned int g_ctr;               // global ticket (reset by final block)

// ---------------------------------------------------------------------------
// Single fused kernel. grid = (CHUNKS, NBATCH, 2), block = 512.
// Phase 1: warp-private shared histogram, store per-block partial.
// Phase 2: last block of each batch (ticket) computes that batch's KL inline,
//          overlapped with other batches' histogram work.
// Phase 3: last batch-winner does the deterministic 64-way final sum.
// ---------------------------------------------------------------------------
__global__ void __launch_bounds__(HIST_THREADS) fused_kernel(
    const float4* __restrict__ feat_s, const float4* __restrict__ feat_t,
    float* __restrict__ out) {

    __shared__ unsigned int sh[WARPS_PER_BLOCK][NBINS];

    #pragma unroll
    for (int i = threadIdx.x; i < WARPS_PER_BLOCK * NBINS; i += HIST_THREADS)
        (&sh[0][0])[i] = 0u;
    __syncthreads();

    const float4* __restrict__ src = (blockIdx.z == 0) ? feat_s : feat_t;
    const int batch = blockIdx.y;
    const size_t base = (size_t)batch * F4_PER_BATCH
                      + (size_t)blockIdx.x * F4_PER_CHUNK;

    unsigned int* myh = sh[threadIdx.x >> 5];

    #pragma unroll 8
    for (int i = threadIdx.x; i < F4_PER_CHUNK; i += HIST_THREADS) {
        float4 v = __ldcs(&src[base + i]);   // streamed: read-once data
        atomicAdd(&myh[(int)v.x], 1u);
        atomicAdd(&myh[(int)v.y], 1u);
        atomicAdd(&myh[(int)v.z], 1u);
        atomicAdd(&myh[(int)v.w], 1u);
    }
    __syncthreads();

    // reduce warp copies; plain store of the partial (overwrites old replay)
    if (threadIdx.x < NBINS) {
        unsigned int sum = 0;
        #pragma unroll
        for (int w = 0; w < WARPS_PER_BLOCK; w++) sum += sh[w][threadIdx.x];
        g_part[blockIdx.z][batch][blockIdx.x][threadIdx.x] = sum;
    }
    __syncthreads();

    // ---- per-batch ticket ----
    __shared__ unsigned int s_bticket;
    if (threadIdx.x == 0) {
        __threadfence();
        s_bticket = atomicAdd(&g_bctr[batch], 1u);
    }
    __syncthreads();
    if (s_bticket != BLOCKS_PER_BATCH - 1) return;

    // ======== this block is last for its batch: compute KL(batch) ========
    __threadfence();  // acquire: make all partials of this batch visible

    const int b = threadIdx.x;            // bin id for threads < NBINS
    __shared__ float rs[NBINS];
    __shared__ float rt[NBINS];

    float es = 0.f, et = 0.f, as_ = 0.f, at_ = 0.f;
    if (b < NBINS) {
        unsigned int cs = 0, ct = 0;
        #pragma unroll
        for (int c = 0; c < CHUNKS; c++) {
            cs += *((volatile unsigned int*)&g_part[0][batch][c][b]);
            ct += *((volatile unsigned int*)&g_part[1][batch][c][b]);
        }
        as_ = (float)cs + 1e-8f;
        at_ = (float)ct + 1e-8f;
        es = sqrtf(sqrtf(as_));           // (a)^(1/T), T = 4
        et = sqrtf(sqrtf(at_));
        rs[b] = es; rt[b] = et;
    }
    __syncthreads();
    #pragma unroll
    for (int s = NBINS / 2; s > 0; s >>= 1) {
        if (b < s) { rs[b] += rs[b + s]; rt[b] += rt[b + s]; }
        __syncthreads();
    }
    float Ss = rs[0];
    float St = rt[0];
    __syncthreads();

    if (b < NBINS) {
        float pt = et / St;                                   // softmax target
        float diff = 0.25f * logf(at_ / as_) - logf(St / Ss); // log p_t - log p_s
        rs[b] = pt * diff;
    }
    __syncthreads();
    #pragma unroll
    for (int s = NBINS / 2; s > 0; s >>= 1) {
        if (b < s) rs[b] += rs[b + s];
        __syncthreads();
    }

    // publish per-batch KL, reset batch ticket, take global ticket
    __shared__ unsigned int s_ticket;
    if (threadIdx.x == 0) {
        g_kl[batch] = rs[0];
        g_bctr[batch] = 0;                 // ready for next graph replay
        __threadfence();
        s_ticket = atomicAdd(&g_ctr, 1u);
    }
    __syncthreads();
    if (s_ticket != NBATCH - 1) return;

    // ======== very last batch-winner: deterministic final sum ========
    __threadfence();
    __shared__ float red[NBATCH];
    if (threadIdx.x < NBATCH) red[threadIdx.x] = *((volatile float*)&g_kl[threadIdx.x]);
    __syncthreads();
    #pragma unroll
    for (int s = NBATCH / 2; s > 0; s >>= 1) {
        if (threadIdx.x < s) red[threadIdx.x] += red[threadIdx.x + s];
        __syncthreads();
    }
    if (threadIdx.x == 0) {
        out[0] = red[0] * (16.0f / (float)NBATCH);  // * T^2 / N
        g_ctr = 0;                                  // ready for next replay
    }
}

// ---------------------------------------------------------------------------
extern "C" void kernel_launch(void* const* d_in, const int* in_sizes, int n_in,
                              void* d_out, int out_size) {
    const float4* feat_s = (const float4*)d_in[0];
    const float4* feat_t = (const float4*)d_in[1];
    float* out = (float*)d_out;

    (void)in_sizes; (void)n_in; (void)out_size;

    dim3 grid(CHUNKS, NBATCH, 2);
    fused_kernel<<<grid, HIST_THREADS>>>(feat_s, feat_t, out);
}

// round 6
// speedup vs baseline: 1.0173x; 1.0173x over previous
#include <cuda_runtime.h>

// Problem constants
#define NBATCH 64
#define NBINS  256
#define ELEMS_PER_BATCH (256*32*32)          // 262144 floats per batch per tensor
#define F4_PER_BATCH    (ELEMS_PER_BATCH/4)  // 65536 float4
#define CHUNKS 4                             // blocks per (batch, tensor)
#define F4_PER_CHUNK (F4_PER_BATCH/CHUNKS)   // 16384 float4 per block
#define HIST_THREADS 512
#define BLOCKS_PER_BATCH (2*CHUNKS)          // 8 (both tensors)

// Scratch (no device allocation allowed).
// Partials are STORED (not accumulated) -> no zeroing pass needed.
__device__ unsigned int g_part[2][NBATCH][CHUNKS][NBINS];
__device__ float        g_kl[NBATCH];
__device__ unsigned int g_bctr[NBATCH];      // per-batch tickets (reset by winner)
__device__ unsigned int g_ctr;               // global ticket (reset by final block)

// ---------------------------------------------------------------------------
// Single fused kernel. grid = (CHUNKS, NBATCH, 2), block = 512.
// Histogram layout: sh[bin][lane] — every lane only touches its own bank
// (addr % 32 == laneid), so smem atomics are bank-conflict-free by
// construction. Cross-warp same-(bin,lane) collisions are the only
// serialization and are rare for random bins.
// ---------------------------------------------------------------------------
__global__ void __launch_bounds__(HIST_THREADS) fused_kernel(
    const float4* __restrict__ feat_s, const float4* __restrict__ feat_t,
    float* __restrict__ out) {

    __shared__ unsigned int sh[NBINS][32];   // 32 KB: [bin][lane-column]

    #pragma unroll
    for (int i = threadIdx.x; i < NBINS * 32; i += HIST_THREADS)
        (&sh[0][0])[i] = 0u;
    __syncthreads();

    const float4* __restrict__ src = (blockIdx.z == 0) ? feat_s : feat_t;
    const int batch = blockIdx.y;
    const size_t base = (size_t)batch * F4_PER_BATCH
                      + (size_t)blockIdx.x * F4_PER_CHUNK;
    const int lane = threadIdx.x & 31;

    #pragma unroll 8
    for (int i = threadIdx.x; i < F4_PER_CHUNK; i += HIST_THREADS) {
        float4 v = __ldcs(&src[base + i]);   // streamed: read-once data
        atomicAdd(&sh[(int)v.x][lane], 1u);
        atomicAdd(&sh[(int)v.y][lane], 1u);
        atomicAdd(&sh[(int)v.z][lane], 1u);
        atomicAdd(&sh[(int)v.w][lane], 1u);
    }
    __syncthreads();

    // reduce 32 lane-columns per bin; rotated reads keep banks conflict-free
    if (threadIdx.x < NBINS) {
        const int b = threadIdx.x;
        unsigned int sum = 0;
        #pragma unroll
        for (int i = 0; i < 32; i++) sum += sh[b][(i + b) & 31];
        g_part[blockIdx.z][batch][blockIdx.x][b] = sum;
    }
    __syncthreads();

    // ---- per-batch ticket ----
    __shared__ unsigned int s_bticket;
    if (threadIdx.x == 0) {
        __threadfence();
        s_bticket = atomicAdd(&g_bctr[batch], 1u);
    }
    __syncthreads();
    if (s_bticket != BLOCKS_PER_BATCH - 1) return;

    // ======== this block is last for its batch: compute KL(batch) ========
    __threadfence();  // acquire: make all partials of this batch visible

    const int b = threadIdx.x;            // bin id for threads < NBINS
    __shared__ float rs[NBINS];
    __shared__ float rt[NBINS];

    float es = 0.f, et = 0.f, as_ = 0.f, at_ = 0.f;
    if (b < NBINS) {
        unsigned int cs = 0, ct = 0;
        #pragma unroll
        for (int c = 0; c < CHUNKS; c++) {
            cs += *((volatile unsigned int*)&g_part[0][batch][c][b]);
            ct += *((volatile unsigned int*)&g_part[1][batch][c][b]);
        }
        as_ = (float)cs + 1e-8f;
        at_ = (float)ct + 1e-8f;
        es = sqrtf(sqrtf(as_));           // (a)^(1/T), T = 4
        et = sqrtf(sqrtf(at_));
        rs[b] = es; rt[b] = et;
    }
    __syncthreads();
    #pragma unroll
    for (int s = NBINS / 2; s > 0; s >>= 1) {
        if (b < s) { rs[b] += rs[b + s]; rt[b] += rt[b + s]; }
        __syncthreads();
    }
    float Ss = rs[0];
    float St = rt[0];
    __syncthreads();

    if (b < NBINS) {
        float pt = et / St;                                   // softmax target
        float diff = 0.25f * logf(at_ / as_) - logf(St / Ss); // log p_t - log p_s
        rs[b] = pt * diff;
    }
    __syncthreads();
    #pragma unroll
    for (int s = NBINS / 2; s > 0; s >>= 1) {
        if (b < s) rs[b] += rs[b + s];
        __syncthreads();
    }

    // publish per-batch KL, reset batch ticket, take global ticket
    __shared__ unsigned int s_ticket;
    if (threadIdx.x == 0) {
        g_kl[batch] = rs[0];
        g_bctr[batch] = 0;                 // ready for next graph replay
        __threadfence();
        s_ticket = atomicAdd(&g_ctr, 1u);
    }
    __syncthreads();
    if (s_ticket != NBATCH - 1) return;

    // ======== very last batch-winner: deterministic final sum ========
    __threadfence();
    __shared__ float red[NBATCH];
    if (threadIdx.x < NBATCH) red[threadIdx.x] = *((volatile float*)&g_kl[threadIdx.x]);
    __syncthreads();
    #pragma unroll
    for (int s = NBATCH / 2; s > 0; s >>= 1) {
        if (threadIdx.x < s) red[threadIdx.x] += red[threadIdx.x + s];
        __syncthreads();
    }
    if (threadIdx.x == 0) {
        out[0] = red[0] * (16.0f / (float)NBATCH);  // * T^2 / N
        g_ctr = 0;                                  // ready for next replay
    }
}

// ---------------------------------------------------------------------------
extern "C" void kernel_launch(void* const* d_in, const int* in_sizes, int n_in,
                              void* d_out, int out_size) {
    const float4* feat_s = (const float4*)d_in[0];
    const float4* feat_t = (const float4*)d_in[1];
    float* out = (float*)d_out;

    (void)in_sizes; (void)n_in; (void)out_size;

    dim3 grid(CHUNKS, NBATCH, 2);
    fused_kernel<<<grid, HIST_THREADS>>>(feat_s, feat_t, out);
}

// round 7
// speedup vs baseline: 1.0395x; 1.0218x over previous
#include <cuda_runtime.h>

// Problem constants
#define NBATCH 64
#define NBINS  256
#define ELEMS_PER_BATCH (256*32*32)          // 262144 floats per batch per tensor
#define F4_PER_BATCH    (ELEMS_PER_BATCH/4)  // 65536 float4
#define CHUNKS 2                             // blocks per (batch, tensor)
#define F4_PER_CHUNK (F4_PER_BATCH/CHUNKS)   // 32768 float4 per block
#define HIST_THREADS 512
#define BLOCKS_PER_BATCH (2*CHUNKS)          // 4 (both tensors)
#define BATCH_F4 8                           // float4 held in regs per iteration

// Scratch (no device allocation allowed).
// Partials are STORED (not accumulated) -> no zeroing pass needed.
__device__ unsigned int g_part[2][NBATCH][CHUNKS][NBINS];
__device__ float        g_kl[NBATCH];
__device__ unsigned int g_bctr[NBATCH];      // per-batch tickets (reset by winner)
__device__ unsigned int g_ctr;               // global ticket (reset by final block)

// ---------------------------------------------------------------------------
// Single fused kernel. grid = (CHUNKS, NBATCH, 2) = 256 blocks, block = 512.
// 2 blocks/SM -> all 256 blocks resident (single wave), 64-reg budget.
// Inner loop: 8 float4 batched into registers (MLP>=8 DRAM lines/warp),
// then 32 bank-exclusive smem atomics (sh[bin][lane], zero conflicts).
// ---------------------------------------------------------------------------
__global__ void __launch_bounds__(HIST_THREADS, 2) fused_kernel(
    const float4* __restrict__ feat_s, const float4* __restrict__ feat_t,
    float* __restrict__ out) {

    __shared__ unsigned int sh[NBINS][32];   // 32 KB: [bin][lane-column]

    #pragma unroll
    for (int i = threadIdx.x; i < NBINS * 32; i += HIST_THREADS)
        (&sh[0][0])[i] = 0u;
    __syncthreads();

    const float4* __restrict__ src = (blockIdx.z == 0) ? feat_s : feat_t;
    const int batch = blockIdx.y;
    const size_t base = (size_t)batch * F4_PER_BATCH
                      + (size_t)blockIdx.x * F4_PER_CHUNK;
    const int lane = threadIdx.x & 31;

    // 32768 float4 per block / 512 threads = 64 per thread = 8 iters x 8 loads
    #pragma unroll 1
    for (int it = 0; it < F4_PER_CHUNK; it += BATCH_F4 * HIST_THREADS) {
        float4 v[BATCH_F4];
        #pragma unroll
        for (int k = 0; k < BATCH_F4; k++)
            v[k] = __ldcs(&src[base + it + k * HIST_THREADS + threadIdx.x]);
        #pragma unroll
        for (int k = 0; k < BATCH_F4; k++) {
            atomicAdd(&sh[(int)v[k].x][lane], 1u);
            atomicAdd(&sh[(int)v[k].y][lane], 1u);
            atomicAdd(&sh[(int)v[k].z][lane], 1u);
            atomicAdd(&sh[(int)v[k].w][lane], 1u);
        }
    }
    __syncthreads();

    // reduce 32 lane-columns per bin; rotated reads keep banks conflict-free
    if (threadIdx.x < NBINS) {
        const int b = threadIdx.x;
        unsigned int sum = 0;
        #pragma unroll
        for (int i = 0; i < 32; i++) sum += sh[b][(i + b) & 31];
        g_part[blockIdx.z][batch][blockIdx.x][b] = sum;
    }
    __syncthreads();

    // ---- per-batch ticket ----
    __shared__ unsigned int s_bticket;
    if (threadIdx.x == 0) {
        __threadfence();
        s_bticket = atomicAdd(&g_bctr[batch], 1u);
    }
    __syncthreads();
    if (s_bticket != BLOCKS_PER_BATCH - 1) return;

    // ======== this block is last for its batch: compute KL(batch) ========
    __threadfence();  // acquire: make all partials of this batch visible

    const int b = threadIdx.x;            // bin id for threads < NBINS
    __shared__ float rs[NBINS];
    __shared__ float rt[NBINS];

    float es = 0.f, et = 0.f, as_ = 0.f, at_ = 0.f;
    if (b < NBINS) {
        unsigned int cs = 0, ct = 0;
        #pragma unroll
        for (int c = 0; c < CHUNKS; c++) {
            cs += *((volatile unsigned int*)&g_part[0][batch][c][b]);
            ct += *((volatile unsigned int*)&g_part[1][batch][c][b]);
        }
        as_ = (float)cs + 1e-8f;
        at_ = (float)ct + 1e-8f;
        es = sqrtf(sqrtf(as_));           // (a)^(1/T), T = 4
        et = sqrtf(sqrtf(at_));
        rs[b] = es; rt[b] = et;
    }
    __syncthreads();
    #pragma unroll
    for (int s = NBINS / 2; s > 0; s >>= 1) {
        if (b < s) { rs[b] += rs[b + s]; rt[b] += rt[b + s]; }
        __syncthreads();
    }
    float Ss = rs[0];
    float St = rt[0];
    __syncthreads();

    if (b < NBINS) {
        float pt = et / St;                                   // softmax target
        float diff = 0.25f * logf(at_ / as_) - logf(St / Ss); // log p_t - log p_s
        rs[b] = pt * diff;
    }
    __syncthreads();
    #pragma unroll
    for (int s = NBINS / 2; s > 0; s >>= 1) {
        if (b < s) rs[b] += rs[b + s];
        __syncthreads();
    }

    // publish per-batch KL, reset batch ticket, take global ticket
    __shared__ unsigned int s_ticket;
    if (threadIdx.x == 0) {
        g_kl[batch] = rs[0];
        g_bctr[batch] = 0;                 // ready for next graph replay
        __threadfence();
        s_ticket = atomicAdd(&g_ctr, 1u);
    }
    __syncthreads();
    if (s_ticket != NBATCH - 1) return;

    // ======== very last batch-winner: deterministic final sum ========
    __threadfence();
    __shared__ float red[NBATCH];
    if (threadIdx.x < NBATCH) red[threadIdx.x] = *((volatile float*)&g_kl[threadIdx.x]);
    __syncthreads();
    #pragma unroll
    for (int s = NBATCH / 2; s > 0; s >>= 1) {
        if (threadIdx.x < s) red[threadIdx.x] += red[threadIdx.x + s];
        __syncthreads();
    }
    if (threadIdx.x == 0) {
        out[0] = red[0] * (16.0f / (float)NBATCH);  // * T^2 / N
        g_ctr = 0;                                  // ready for next replay
    }
}

// ---------------------------------------------------------------------------
extern "C" void kernel_launch(void* const* d_in, const int* in_sizes, int n_in,
                              void* d_out, int out_size) {
    const float4* feat_s = (const float4*)d_in[0];
    const float4* feat_t = (const float4*)d_in[1];
    float* out = (float*)d_out;

    (void)in_sizes; (void)n_in; (void)out_size;

    dim3 grid(CHUNKS, NBATCH, 2);
    fused_kernel<<<grid, HIST_THREADS>>>(feat_s, feat_t, out);
}